// round 3
// baseline (speedup 1.0000x reference)
#include <cuda_runtime.h>
#include <cstdint>

#define B      16
#define T      4096
#define D      256
#define TOPK   7

// padded smem index: +1 float2 every 16
#define SPAD(i) ((i) + ((i) >> 4))
#define SER_PAD 4352

// per-series params: float4(k_as_int_bits, C=Re/1024, S=Im/1024, 0)
__device__ float4 g_params[B * D * TOPK];

__device__ __forceinline__ float2 cmul(float2 a, float2 b) {
    return make_float2(a.x * b.x - a.y * b.y, a.x * b.y + a.y * b.x);
}
__device__ __forceinline__ float2 cmulf(float2 a, float br, float bi) {
    return make_float2(a.x * br - a.y * bi, a.x * bi + a.y * br);
}

__device__ __forceinline__ void bf4(float2& a0, float2& a1, float2& a2, float2& a3) {
    float2 t0 = make_float2(a0.x + a2.x, a0.y + a2.y);
    float2 t1 = make_float2(a0.x - a2.x, a0.y - a2.y);
    float2 t2 = make_float2(a1.x + a3.x, a1.y + a3.y);
    float2 t3 = make_float2(a1.x - a3.x, a1.y - a3.y);
    a0 = make_float2(t0.x + t2.x, t0.y + t2.y);
    a1 = make_float2(t1.x + t3.y, t1.y - t3.x);   // t1 - i*t3
    a2 = make_float2(t0.x - t2.x, t0.y - t2.y);
    a3 = make_float2(t1.x - t3.y, t1.y + t3.x);   // t1 + i*t3
}

// 16-point forward DFT, natural-order input.
// Y[alpha] ends in slot ((alpha&3)<<2)|(alpha>>2).
__device__ __forceinline__ void dft16(float2* r) {
    const float C1 = 0.9238795325112867f;
    const float S1 = 0.3826834323650898f;
    const float A  = 0.7071067811865476f;
    bf4(r[0], r[4], r[8],  r[12]);
    bf4(r[1], r[5], r[9],  r[13]);
    r[5]  = cmulf(r[5],  C1, -S1);
    r[9]  = cmulf(r[9],  A,  -A);
    r[13] = cmulf(r[13], S1, -C1);
    bf4(r[2], r[6], r[10], r[14]);
    r[6]  = cmulf(r[6],  A,  -A);
    r[10] = make_float2(r[10].y, -r[10].x);
    r[14] = cmulf(r[14], -A, -A);
    bf4(r[3], r[7], r[11], r[15]);
    r[7]  = cmulf(r[7],  S1, -C1);
    r[11] = cmulf(r[11], -A, -A);
    r[15] = cmulf(r[15], -C1, S1);
    bf4(r[0],  r[1],  r[2],  r[3]);
    bf4(r[4],  r[5],  r[6],  r[7]);
    bf4(r[8],  r[9],  r[10], r[11]);
    bf4(r[12], r[13], r[14], r[15]);
}

// ---------------------------------------------------------------------------
// Kernel 1: 256 threads, 2 packed complex series per block (4 channels).
// Each thread runs the radix-16 passes for BOTH series sequentially, so r[16]
// registers are reused and twiddles (functions of tl only) are computed once.
// No launch-bounds register cap -> no spills.
// ---------------------------------------------------------------------------
__global__ __launch_bounds__(256)
void fft_topk_kernel(const float* __restrict__ x) {
    extern __shared__ float2 sm[];
    float2* zz   = sm;                       // 2 * SER_PAD
    float2* red  = sm + 2 * SER_PAD;         // [4 channels][8 warps]
    int*    wink = (int*)(red + 32);         // [4]

    const int tid = threadIdx.x;
    const int b   = blockIdx.x >> 6;
    const int d0  = (blockIdx.x & 63) * 4;
    const int tl  = tid;                     // lane within each series (0..255)

    // coalesced-ish load: float4 = 4 channels -> 2 complex series
    for (int t = tid; t < T; t += 256) {
        float4 v = *reinterpret_cast<const float4*>(
            x + ((size_t)(b * T + t)) * D + d0);
        zz[SPAD(t)]           = make_float2(v.x, v.y);
        zz[SER_PAD + SPAD(t)] = make_float2(v.z, v.w);
    }
    __syncthreads();

    float2 r[16];

    // ---------------- pass 1 twiddle base: W_256^{b2}, b2 = tl>>4 ----------
    float2 p1w1;
    {
        float s, c; sincospif((float)(tl >> 4) * (1.0f / 128.0f), &s, &c);
        p1w1 = make_float2(c, -s);
    }
    // pass 1: per-thread exclusive index set -> both series, then one sync
    #pragma unroll
    for (int sser = 0; sser < 2; sser++) {
        float2* Z = zz + sser * SER_PAD;
        #pragma unroll
        for (int a = 0; a < 16; a++) r[a] = Z[SPAD(a * 256 + tl)];
        dft16(r);
        float2 w = p1w1;
        #pragma unroll
        for (int al = 1; al < 16; al++) {
            const int sl = ((al & 3) << 2) | (al >> 2);
            r[sl] = cmul(r[sl], w);
            w = cmul(w, p1w1);
        }
        #pragma unroll
        for (int al = 0; al < 16; al++)
            Z[SPAD(al * 256 + tl)] = r[((al & 3) << 2) | (al >> 2)];
    }
    __syncthreads();

    // ---------------- pass 2: twiddles depend on (alpha, c) = f(tl) --------
    const int alpha = tl >> 4, cc = tl & 15;
    float2 p2w0, p2st;
    {
        float s0, c0, s1, c1;
        sincospif((float)(cc * alpha) * (1.0f / 2048.0f), &s0, &c0);
        sincospif((float)cc * (1.0f / 128.0f), &s1, &c1);
        p2w0 = make_float2(c0, -s0);
        p2st = make_float2(c1, -s1);
    }
    #pragma unroll
    for (int sser = 0; sser < 2; sser++) {
        float2* Z = zz + sser * SER_PAD;
        #pragma unroll
        for (int bb = 0; bb < 16; bb++)
            r[bb] = Z[SPAD(alpha * 256 + bb * 16 + cc)];
        dft16(r);
        float2 w = p2w0;
        #pragma unroll
        for (int be = 0; be < 16; be++) {
            const int sl = ((be & 3) << 2) | (be >> 2);
            r[sl] = cmul(r[sl], w);
            w = cmul(w, p2st);
        }
        #pragma unroll
        for (int be = 0; be < 16; be++)
            Z[SPAD(alpha * 256 + be * 16 + cc)] = r[((be & 3) << 2) | (be >> 2)];
    }
    __syncthreads();

    // ---------------- pass 3: scatter; needs read-all-before-write per series
    {
        const int beta = tl & 15;   // reuse alpha = tl>>4
        float2* Z0 = zz;
        #pragma unroll
        for (int c2 = 0; c2 < 16; c2++)
            r[c2] = Z0[SPAD(alpha * 256 + beta * 16 + c2)];
        __syncthreads();
        dft16(r);
        #pragma unroll
        for (int ga = 0; ga < 16; ga++)
            Z0[SPAD(ga * 256 + beta * 16 + alpha)] = r[((ga & 3) << 2) | (ga >> 2)];

        float2* Z1 = zz + SER_PAD;
        #pragma unroll
        for (int c2 = 0; c2 < 16; c2++)
            r[c2] = Z1[SPAD(alpha * 256 + beta * 16 + c2)];
        __syncthreads();
        dft16(r);
        #pragma unroll
        for (int ga = 0; ga < 16; ga++)
            Z1[SPAD(ga * 256 + beta * 16 + alpha)] = r[((ga & 3) << 2) | (ga >> 2)];
    }
    __syncthreads();

    // ---------------- magnitudes: 4 real channels, 8 bins each -------------
    float mg[4][8];
    #pragma unroll
    for (int sser = 0; sser < 2; sser++) {
        float2* Z = zz + sser * SER_PAD;
        #pragma unroll
        for (int m = 0; m < 8; m++) {
            int k = m * 256 + tl;
            const bool valid = (k != 0);
            int kk = valid ? k : 1;
            float2 Zk = Z[SPAD(kk)];
            float2 Zn = Z[SPAD(4096 - kk)];
            float reA = 0.5f * (Zk.x + Zn.x), imA = 0.5f * (Zk.y - Zn.y);
            float reB = 0.5f * (Zk.y + Zn.y), imB = 0.5f * (Zn.x - Zk.x);
            mg[sser * 2 + 0][m] = valid ? (reA * reA + imA * imA) : -1.0f;
            mg[sser * 2 + 1][m] = valid ? (reB * reB + imB * imB) : -1.0f;
        }
    }

    const int wrp = tid >> 5;
    for (int round = 0; round < TOPK; round++) {
        #pragma unroll
        for (int q = 0; q < 4; q++) {
            float bm = mg[q][0]; int bk = tl;
            #pragma unroll
            for (int m = 1; m < 8; m++)
                if (mg[q][m] > bm) { bm = mg[q][m]; bk = m * 256 + tl; }
            #pragma unroll
            for (int o = 16; o > 0; o >>= 1) {
                float om = __shfl_down_sync(0xFFFFFFFFu, bm, o);
                int   ok = __shfl_down_sync(0xFFFFFFFFu, bk, o);
                if (om > bm) { bm = om; bk = ok; }
            }
            if ((tid & 31) == 0)
                red[q * 8 + wrp] = make_float2(bm, __int_as_float(bk));
        }
        __syncthreads();

        if (tid < 4) {                 // tid = q = series*2 + ch
            const int s2 = tid >> 1, ch = tid & 1;
            float wm = -2.0f; int wk = 1;
            #pragma unroll
            for (int u = 0; u < 8; u++) {
                float2 e = red[tid * 8 + u];
                if (e.x > wm) { wm = e.x; wk = __float_as_int(e.y); }
            }
            float2* Zs = zz + s2 * SER_PAD;
            float2 Zk = Zs[SPAD(wk)];
            float2 Zn = Zs[SPAD(4096 - wk)];
            float re, im;
            if (!ch) { re = 0.5f * (Zk.x + Zn.x); im = 0.5f * (Zk.y - Zn.y); }
            else     { re = 0.5f * (Zk.y + Zn.y); im = 0.5f * (Zn.x - Zk.x); }
            g_params[(size_t)(b * D + d0 + 2 * s2 + ch) * TOPK + round] =
                make_float4(__int_as_float(wk), re * (1.0f / 1024.0f),
                            im * (1.0f / 1024.0f), 0.0f);
            wink[tid] = wk;
        }
        __syncthreads();

        #pragma unroll
        for (int q = 0; q < 4; q++) {
            const int wq = wink[q];
            #pragma unroll
            for (int m = 0; m < 8; m++)
                if (wq == m * 256 + tl) mg[q][m] = -1.0f;
        }
        __syncthreads();
    }
}

// ---------------------------------------------------------------------------
// Kernel 2: Chebyshev recurrence reconstruction, 64-sample chunks (1024 blocks)
// ---------------------------------------------------------------------------
__global__ __launch_bounds__(256)
void reconstruct_kernel(float* __restrict__ out) {
    const int d  = threadIdx.x;
    const int b  = blockIdx.y;
    const int t0 = blockIdx.x * 64;
    const size_t series = (size_t)b * D + d;

    float twoC[TOPK], g[TOPK], gp[TOPK];
    #pragma unroll
    for (int j = 0; j < TOPK; j++) {
        float4 p = g_params[series * TOPK + j];
        int k = __float_as_int(p.x);
        float C = p.y, S = p.z;
        int m0 = (k * (t0 - 1)) & (T - 1);
        int m1 = (k * t0) & (T - 1);
        float s, c;
        sincospif((float)m0 * (1.0f / 2048.0f), &s, &c);
        gp[j] = C * c - S * s;
        sincospif((float)m1 * (1.0f / 2048.0f), &s, &c);
        g[j] = C * c - S * s;
        twoC[j] = 2.0f * cospif((float)k * (1.0f / 2048.0f));
    }

    float* orow = out + ((size_t)(b * T + t0)) * D + d;
    #pragma unroll 4
    for (int tt = 0; tt < 64; tt += 2) {
        float a0 = 0.0f;
        #pragma unroll
        for (int j = 0; j < TOPK; j++) a0 += g[j];
        orow[(size_t)tt * D] = a0;
        #pragma unroll
        for (int j = 0; j < TOPK; j++)
            gp[j] = fmaf(twoC[j], g[j], -gp[j]);
        float a1 = 0.0f;
        #pragma unroll
        for (int j = 0; j < TOPK; j++) a1 += gp[j];
        orow[(size_t)(tt + 1) * D] = a1;
        #pragma unroll
        for (int j = 0; j < TOPK; j++)
            g[j] = fmaf(twoC[j], gp[j], -g[j]);
    }
}

// ---------------------------------------------------------------------------
extern "C" void kernel_launch(void* const* d_in, const int* in_sizes, int n_in,
                              void* d_out, int out_size) {
    const float* x = (const float*)d_in[0];
    float* out = (float*)d_out;

    const size_t smem_bytes = (2 * SER_PAD + 32) * sizeof(float2) + 4 * sizeof(int);
    cudaFuncSetAttribute(fft_topk_kernel,
                         cudaFuncAttributeMaxDynamicSharedMemorySize,
                         (int)smem_bytes);

    fft_topk_kernel<<<B * D / 4, 256, smem_bytes>>>(x);
    reconstruct_kernel<<<dim3(T / 64, B), 256>>>(out);
}

// round 4
// speedup vs baseline: 1.2848x; 1.2848x over previous
#include <cuda_runtime.h>
#include <cstdint>

#define B      16
#define T      4096
#define D      256
#define TOPK   7
#define NTHR   1024
#define NBLK   (B * D / 8)          // 512 blocks, 8 channels each

// padded smem index: +1 float2 every 16
#define SPAD(i) ((i) + ((i) >> 4))
#define SER_PAD 4356                // 4350 rounded up + 6 -> planes staggered by 8 banks

// per-series params: float4(k_as_int_bits, C=Re/1024, S=Im/1024, twoC)
__device__ float4 g_params[B * D * TOPK];
// cos table: g_costab[m] = cos(pi*m/2048) = cos(2*pi*m/4096)
__device__ float  g_costab[T];

__device__ __forceinline__ float2 cmul(float2 a, float2 b) {
    return make_float2(a.x * b.x - a.y * b.y, a.x * b.y + a.y * b.x);
}
__device__ __forceinline__ float2 cmulf(float2 a, float br, float bi) {
    return make_float2(a.x * br - a.y * bi, a.x * bi + a.y * br);
}

__device__ __forceinline__ void bf4(float2& a0, float2& a1, float2& a2, float2& a3) {
    float2 t0 = make_float2(a0.x + a2.x, a0.y + a2.y);
    float2 t1 = make_float2(a0.x - a2.x, a0.y - a2.y);
    float2 t2 = make_float2(a1.x + a3.x, a1.y + a3.y);
    float2 t3 = make_float2(a1.x - a3.x, a1.y - a3.y);
    a0 = make_float2(t0.x + t2.x, t0.y + t2.y);
    a1 = make_float2(t1.x + t3.y, t1.y - t3.x);   // t1 - i*t3
    a2 = make_float2(t0.x - t2.x, t0.y - t2.y);
    a3 = make_float2(t1.x - t3.y, t1.y + t3.x);   // t1 + i*t3
}

// 16-point forward DFT, natural-order input.
// Y[alpha] ends in slot ((alpha&3)<<2)|(alpha>>2).
__device__ __forceinline__ void dft16(float2* r) {
    const float C1 = 0.9238795325112867f;
    const float S1 = 0.3826834323650898f;
    const float A  = 0.7071067811865476f;
    bf4(r[0], r[4], r[8],  r[12]);
    bf4(r[1], r[5], r[9],  r[13]);
    r[5]  = cmulf(r[5],  C1, -S1);
    r[9]  = cmulf(r[9],  A,  -A);
    r[13] = cmulf(r[13], S1, -C1);
    bf4(r[2], r[6], r[10], r[14]);
    r[6]  = cmulf(r[6],  A,  -A);
    r[10] = make_float2(r[10].y, -r[10].x);
    r[14] = cmulf(r[14], -A, -A);
    bf4(r[3], r[7], r[11], r[15]);
    r[7]  = cmulf(r[7],  S1, -C1);
    r[11] = cmulf(r[11], -A, -A);
    r[15] = cmulf(r[15], -C1, S1);
    bf4(r[0],  r[1],  r[2],  r[3]);
    bf4(r[4],  r[5],  r[6],  r[7]);
    bf4(r[8],  r[9],  r[10], r[11]);
    bf4(r[12], r[13], r[14], r[15]);
}

// ---------------------------------------------------------------------------
// Kernel 1: 1024 threads, 8 channels -> 4 packed complex series per block.
// One series slice per thread (tid>>8 = series, tid&255 = lane), fully parallel.
// Loads are 32B-per-row -> 100% sector utilization.
// ---------------------------------------------------------------------------
__global__ __launch_bounds__(NTHR, 1)
void fft_topk_kernel(const float* __restrict__ x) {
    extern __shared__ float2 sm[];
    float2* zz   = sm;                       // 4 * SER_PAD
    float2* red  = sm + 4 * SER_PAD;         // [8 channels][8 warps]
    int*    wink = (int*)(red + 64);         // [8]

    const int tid = threadIdx.x;
    const int b   = blockIdx.x >> 5;
    const int d0  = (blockIdx.x & 31) * 8;

    // first 16 blocks fill the cos table (done before reconstruct launches)
    if (blockIdx.x < 16 && tid < 256) {
        int m = blockIdx.x * 256 + tid;
        g_costab[m] = cospif((float)m * (1.0f / 2048.0f));
    }

    // load: thread pair covers one 32B row (8 channels); 512 rows per iter
    #pragma unroll
    for (int it = 0; it < 8; it++) {
        int t    = (tid >> 1) + it * 512;
        int half = tid & 1;
        float4 v = *reinterpret_cast<const float4*>(
            x + ((size_t)(b * T + t)) * D + d0 + half * 4);
        int p0 = half * 2;
        zz[p0 * SER_PAD + SPAD(t)]       = make_float2(v.x, v.y);
        zz[(p0 + 1) * SER_PAD + SPAD(t)] = make_float2(v.z, v.w);
    }
    __syncthreads();

    const int sid = tid >> 8;
    const int tl  = tid & 255;
    float2* Z = zz + sid * SER_PAD;
    float2 r[16];

    // ---------------- pass 1: stride 256 ----------------
    #pragma unroll
    for (int a = 0; a < 16; a++) r[a] = Z[SPAD(a * 256 + tl)];
    dft16(r);
    {
        float s, c; sincospif((float)(tl >> 4) * (1.0f / 128.0f), &s, &c);
        float2 w1 = make_float2(c, -s);
        float2 w  = w1;
        #pragma unroll
        for (int al = 1; al < 16; al++) {
            const int sl = ((al & 3) << 2) | (al >> 2);
            r[sl] = cmul(r[sl], w);
            w = cmul(w, w1);
        }
    }
    #pragma unroll
    for (int al = 0; al < 16; al++)
        Z[SPAD(al * 256 + tl)] = r[((al & 3) << 2) | (al >> 2)];
    __syncthreads();

    // ---------------- pass 2: stride 16 ----------------
    const int alpha = tl >> 4, cc = tl & 15;
    {
        #pragma unroll
        for (int bb = 0; bb < 16; bb++)
            r[bb] = Z[SPAD(alpha * 256 + bb * 16 + cc)];
        dft16(r);
        float s0, c0, s1, c1;
        sincospif((float)(cc * alpha) * (1.0f / 2048.0f), &s0, &c0);
        sincospif((float)cc * (1.0f / 128.0f), &s1, &c1);
        float2 w    = make_float2(c0, -s0);
        float2 step = make_float2(c1, -s1);
        #pragma unroll
        for (int be = 0; be < 16; be++) {
            const int sl = ((be & 3) << 2) | (be >> 2);
            r[sl] = cmul(r[sl], w);
            w = cmul(w, step);
        }
        #pragma unroll
        for (int be = 0; be < 16; be++)
            Z[SPAD(alpha * 256 + be * 16 + cc)] = r[((be & 3) << 2) | (be >> 2)];
    }
    __syncthreads();

    // ---------------- pass 3: stride 1, scatter ----------------
    {
        const int beta = tl & 15;
        #pragma unroll
        for (int c2 = 0; c2 < 16; c2++)
            r[c2] = Z[SPAD(alpha * 256 + beta * 16 + c2)];
        __syncthreads();                 // all reads before cross-thread writes
        dft16(r);
        #pragma unroll
        for (int ga = 0; ga < 16; ga++)
            Z[SPAD(ga * 256 + beta * 16 + alpha)] = r[((ga & 3) << 2) | (ga >> 2)];
    }
    __syncthreads();

    // ---------------- magnitudes: 2 real channels per series ---------------
    float magA[8], magB[8];
    #pragma unroll
    for (int m = 0; m < 8; m++) {
        int k = m * 256 + tl;
        const bool valid = (k != 0);
        int kk = valid ? k : 1;
        float2 Zk = Z[SPAD(kk)];
        float2 Zn = Z[SPAD(4096 - kk)];
        float reA = 0.5f * (Zk.x + Zn.x), imA = 0.5f * (Zk.y - Zn.y);
        float reB = 0.5f * (Zk.y + Zn.y), imB = 0.5f * (Zn.x - Zk.x);
        magA[m] = valid ? (reA * reA + imA * imA) : -1.0f;
        magB[m] = valid ? (reB * reB + imB * imB) : -1.0f;
    }

    const int wrp = (tid >> 5) & 7;      // warp within series
    for (int round = 0; round < TOPK; round++) {
        // channel A
        float bm = magA[0]; int bk = tl;
        #pragma unroll
        for (int m = 1; m < 8; m++)
            if (magA[m] > bm) { bm = magA[m]; bk = m * 256 + tl; }
        #pragma unroll
        for (int o = 16; o > 0; o >>= 1) {
            float om = __shfl_down_sync(0xFFFFFFFFu, bm, o);
            int   ok = __shfl_down_sync(0xFFFFFFFFu, bk, o);
            if (om > bm) { bm = om; bk = ok; }
        }
        if ((tl & 31) == 0)
            red[(sid * 2 + 0) * 8 + wrp] = make_float2(bm, __int_as_float(bk));
        // channel B
        bm = magB[0]; bk = tl;
        #pragma unroll
        for (int m = 1; m < 8; m++)
            if (magB[m] > bm) { bm = magB[m]; bk = m * 256 + tl; }
        #pragma unroll
        for (int o = 16; o > 0; o >>= 1) {
            float om = __shfl_down_sync(0xFFFFFFFFu, bm, o);
            int   ok = __shfl_down_sync(0xFFFFFFFFu, bk, o);
            if (om > bm) { bm = om; bk = ok; }
        }
        if ((tl & 31) == 0)
            red[(sid * 2 + 1) * 8 + wrp] = make_float2(bm, __int_as_float(bk));
        __syncthreads();

        if (tid < 8) {                   // tid = channel q = series*2 + ch
            const int s2 = tid >> 1, ch = tid & 1;
            float wm = -2.0f; int wk = 1;
            #pragma unroll
            for (int u = 0; u < 8; u++) {
                float2 e = red[tid * 8 + u];
                if (e.x > wm) { wm = e.x; wk = __float_as_int(e.y); }
            }
            float2* Zs = zz + s2 * SER_PAD;
            float2 Zk = Zs[SPAD(wk)];
            float2 Zn = Zs[SPAD(4096 - wk)];
            float re, im;
            if (!ch) { re = 0.5f * (Zk.x + Zn.x); im = 0.5f * (Zk.y - Zn.y); }
            else     { re = 0.5f * (Zk.y + Zn.y); im = 0.5f * (Zn.x - Zk.x); }
            float twoC = 2.0f * cospif((float)wk * (1.0f / 2048.0f));
            g_params[(size_t)(b * D + d0 + 2 * s2 + ch) * TOPK + round] =
                make_float4(__int_as_float(wk), re * (1.0f / 1024.0f),
                            im * (1.0f / 1024.0f), twoC);
            wink[tid] = wk;
        }
        __syncthreads();

        const int wkA = wink[sid * 2 + 0];
        const int wkB = wink[sid * 2 + 1];
        #pragma unroll
        for (int m = 0; m < 8; m++) {
            if (wkA == m * 256 + tl) magA[m] = -1.0f;
            if (wkB == m * 256 + tl) magB[m] = -1.0f;
        }
        __syncthreads();
    }
}

// ---------------------------------------------------------------------------
// Kernel 2: Chebyshev reconstruction, 128-sample chunks, table-based seeds.
// sin(pi*m/2048) = tab[(m-1024)&4095]. Launched in 4 quarters (toff).
// ---------------------------------------------------------------------------
__global__ __launch_bounds__(256)
void reconstruct_kernel(float* __restrict__ out, int toff) {
    const int d  = threadIdx.x;
    const int b  = blockIdx.y;
    const int t0 = (blockIdx.x + toff) * 128;
    const size_t series = (size_t)b * D + d;

    float twoC[TOPK], g[TOPK], gp[TOPK];
    #pragma unroll
    for (int j = 0; j < TOPK; j++) {
        float4 p = g_params[series * TOPK + j];
        int k = __float_as_int(p.x);
        float C = p.y, S = p.z;
        twoC[j] = p.w;
        int m1 = (k * t0) & (T - 1);
        int m0 = (k * (t0 - 1)) & (T - 1);
        gp[j] = C * g_costab[m0] - S * g_costab[(m0 - 1024) & (T - 1)];
        g[j]  = C * g_costab[m1] - S * g_costab[(m1 - 1024) & (T - 1)];
    }

    float* orow = out + ((size_t)(b * T + t0)) * D + d;
    for (int tt = 0; tt < 128; tt += 2) {
        float a0 = 0.0f;
        #pragma unroll
        for (int j = 0; j < TOPK; j++) a0 += g[j];
        orow[(size_t)tt * D] = a0;
        #pragma unroll
        for (int j = 0; j < TOPK; j++)
            gp[j] = fmaf(twoC[j], g[j], -gp[j]);
        float a1 = 0.0f;
        #pragma unroll
        for (int j = 0; j < TOPK; j++) a1 += gp[j];
        orow[(size_t)(tt + 1) * D] = a1;
        #pragma unroll
        for (int j = 0; j < TOPK; j++)
            g[j] = fmaf(twoC[j], gp[j], -g[j]);
    }
}

// ---------------------------------------------------------------------------
extern "C" void kernel_launch(void* const* d_in, const int* in_sizes, int n_in,
                              void* d_out, int out_size) {
    const float* x = (const float*)d_in[0];
    float* out = (float*)d_out;

    const size_t smem_bytes = (4 * SER_PAD + 64) * sizeof(float2) + 8 * sizeof(int);
    cudaFuncSetAttribute(fft_topk_kernel,
                         cudaFuncAttributeMaxDynamicSharedMemorySize,
                         (int)smem_bytes);

    fft_topk_kernel<<<NBLK, NTHR, smem_bytes>>>(x);
    // 4 quarter-launches (also puts fft_topk at ncu's -s 5 sample position)
    for (int q = 0; q < 4; q++)
        reconstruct_kernel<<<dim3(8, B), 256>>>(out, q * 8);
}

// round 5
// speedup vs baseline: 1.4347x; 1.1167x over previous
#include <cuda_runtime.h>
#include <cstdint>

#define B      16
#define T      4096
#define D      256
#define TOPK   7
#define NBLK   (B * D / 2)          // 2048 blocks, 2 channels (1 complex series) each

// padded smem index: +1 float2 every 16 (conflict-free stride-16 pass)
#define SPAD(i) ((i) + ((i) >> 4))
#define SER_PAD 4356

// per-series params: float4(k_as_int_bits, C=Re/1024, S=Im/1024, twoC)
__device__ float4 g_params[B * D * TOPK];
// g_costab[m] = cos(pi*m/2048) = cos(2*pi*m/4096)
__device__ float  g_costab[T];

__device__ __forceinline__ float2 cmul(float2 a, float2 b) {
    return make_float2(a.x * b.x - a.y * b.y, a.x * b.y + a.y * b.x);
}
__device__ __forceinline__ float2 cmulf(float2 a, float br, float bi) {
    return make_float2(a.x * br - a.y * bi, a.x * bi + a.y * br);
}

__device__ __forceinline__ void bf4(float2& a0, float2& a1, float2& a2, float2& a3) {
    float2 t0 = make_float2(a0.x + a2.x, a0.y + a2.y);
    float2 t1 = make_float2(a0.x - a2.x, a0.y - a2.y);
    float2 t2 = make_float2(a1.x + a3.x, a1.y + a3.y);
    float2 t3 = make_float2(a1.x - a3.x, a1.y - a3.y);
    a0 = make_float2(t0.x + t2.x, t0.y + t2.y);
    a1 = make_float2(t1.x + t3.y, t1.y - t3.x);   // t1 - i*t3
    a2 = make_float2(t0.x - t2.x, t0.y - t2.y);
    a3 = make_float2(t1.x - t3.y, t1.y + t3.x);   // t1 + i*t3
}

// 16-point forward DFT, natural-order input.
// Y[alpha] ends in slot ((alpha&3)<<2)|(alpha>>2).
__device__ __forceinline__ void dft16(float2* r) {
    const float C1 = 0.9238795325112867f;
    const float S1 = 0.3826834323650898f;
    const float A  = 0.7071067811865476f;
    bf4(r[0], r[4], r[8],  r[12]);
    bf4(r[1], r[5], r[9],  r[13]);
    r[5]  = cmulf(r[5],  C1, -S1);
    r[9]  = cmulf(r[9],  A,  -A);
    r[13] = cmulf(r[13], S1, -C1);
    bf4(r[2], r[6], r[10], r[14]);
    r[6]  = cmulf(r[6],  A,  -A);
    r[10] = make_float2(r[10].y, -r[10].x);
    r[14] = cmulf(r[14], -A, -A);
    bf4(r[3], r[7], r[11], r[15]);
    r[7]  = cmulf(r[7],  S1, -C1);
    r[11] = cmulf(r[11], -A, -A);
    r[15] = cmulf(r[15], -C1, S1);
    bf4(r[0],  r[1],  r[2],  r[3]);
    bf4(r[4],  r[5],  r[6],  r[7]);
    bf4(r[8],  r[9],  r[10], r[11]);
    bf4(r[12], r[13], r[14], r[15]);
}

// ---------------------------------------------------------------------------
// Kernel 1: 256 threads, ONE packed complex series (2 channels) per block.
// 4 CTAs/SM. Warp-local top-7 (no block syncs) + single cross-warp merge.
// ---------------------------------------------------------------------------
__global__ __launch_bounds__(256, 4)
void fft_topk_kernel(const float* __restrict__ x) {
    extern __shared__ float2 sm[];
    float2* Z    = sm;                       // SER_PAD
    float2* cand = sm + SER_PAD;             // [2 channels][8 warps * 7]

    const int tid = threadIdx.x;
    const int blk = blockIdx.x;
    const int b   = blk >> 7;                // 128 blocks per batch
    const int d0  = (blk & 127) * 2;
    const int tl  = tid;
    const int lane = tid & 31;
    const int wrp  = tid >> 5;

    // first 16 blocks fill the cos table (done before reconstruct launches)
    if (blk < 16) g_costab[blk * 256 + tid] = cospif((float)(blk * 256 + tid) * (1.0f / 2048.0f));

    // load series: float2 (channels d0, d0+1) per time step
    #pragma unroll
    for (int it = 0; it < 16; it++) {
        int t = tid + it * 256;
        float2 v = *reinterpret_cast<const float2*>(
            x + ((size_t)(b * T + t)) * D + d0);
        Z[SPAD(t)] = v;
    }
    __syncthreads();

    float2 r[16];

    // ---------------- pass 1: stride 256 ----------------
    #pragma unroll
    for (int a = 0; a < 16; a++) r[a] = Z[SPAD(a * 256 + tl)];
    dft16(r);
    {
        float s, c; sincospif((float)(tl >> 4) * (1.0f / 128.0f), &s, &c);
        float2 w1 = make_float2(c, -s);
        float2 w  = w1;
        #pragma unroll
        for (int al = 1; al < 16; al++) {
            const int sl = ((al & 3) << 2) | (al >> 2);
            r[sl] = cmul(r[sl], w);
            w = cmul(w, w1);
        }
    }
    #pragma unroll
    for (int al = 0; al < 16; al++)
        Z[SPAD(al * 256 + tl)] = r[((al & 3) << 2) | (al >> 2)];
    __syncthreads();

    // ---------------- pass 2: stride 16 ----------------
    const int alpha = tl >> 4, cc = tl & 15;
    {
        #pragma unroll
        for (int bb = 0; bb < 16; bb++)
            r[bb] = Z[SPAD(alpha * 256 + bb * 16 + cc)];
        dft16(r);
        float s0, c0, s1, c1;
        sincospif((float)(cc * alpha) * (1.0f / 2048.0f), &s0, &c0);
        sincospif((float)cc * (1.0f / 128.0f), &s1, &c1);
        float2 w    = make_float2(c0, -s0);
        float2 step = make_float2(c1, -s1);
        #pragma unroll
        for (int be = 0; be < 16; be++) {
            const int sl = ((be & 3) << 2) | (be >> 2);
            r[sl] = cmul(r[sl], w);
            w = cmul(w, step);
        }
        #pragma unroll
        for (int be = 0; be < 16; be++)
            Z[SPAD(alpha * 256 + be * 16 + cc)] = r[((be & 3) << 2) | (be >> 2)];
    }
    __syncwarp();          // pass2->pass3 exchange stays within this warp

    // ---------------- pass 3: stride 1, scatter ----------------
    {
        const int beta = tl & 15;
        #pragma unroll
        for (int c2 = 0; c2 < 16; c2++)
            r[c2] = Z[SPAD(alpha * 256 + beta * 16 + c2)];
        __syncthreads();                 // all reads done before scatter writes
        dft16(r);
        #pragma unroll
        for (int ga = 0; ga < 16; ga++)
            Z[SPAD(ga * 256 + beta * 16 + alpha)] = r[((ga & 3) << 2) | (ga >> 2)];
    }
    __syncthreads();

    // ---------------- magnitudes (2 real channels) ----------------
    float magA[8], magB[8];
    #pragma unroll
    for (int m = 0; m < 8; m++) {
        int k = m * 256 + tl;
        const bool valid = (k != 0);
        int kk = valid ? k : 1;
        float2 Zk = Z[SPAD(kk)];
        float2 Zn = Z[SPAD(4096 - kk)];
        float reA = 0.5f * (Zk.x + Zn.x), imA = 0.5f * (Zk.y - Zn.y);
        float reB = 0.5f * (Zk.y + Zn.y), imB = 0.5f * (Zn.x - Zk.x);
        magA[m] = valid ? (reA * reA + imA * imA) : -1.0f;
        magB[m] = valid ? (reB * reB + imB * imB) : -1.0f;
    }

    // ---------------- phase 1: warp-local top-7 (no block syncs) -----------
    #pragma unroll
    for (int r7 = 0; r7 < TOPK; r7++) {
        // channel A
        float bm = magA[0]; int bmi = 0;
        #pragma unroll
        for (int m = 1; m < 8; m++)
            if (magA[m] > bm) { bm = magA[m]; bmi = m; }
        int bk = bmi * 256 + tl;
        #pragma unroll
        for (int o = 16; o > 0; o >>= 1) {
            float om = __shfl_down_sync(0xFFFFFFFFu, bm, o);
            int   ok = __shfl_down_sync(0xFFFFFFFFu, bk, o);
            if (om > bm) { bm = om; bk = ok; }
        }
        bm = __shfl_sync(0xFFFFFFFFu, bm, 0);
        bk = __shfl_sync(0xFFFFFFFFu, bk, 0);
        if ((bk & 255) == tl) magA[bk >> 8] = -1.0f;
        if (lane == r7) cand[wrp * TOPK + r7] = make_float2(bm, __int_as_float(bk));
        // channel B
        bm = magB[0]; bmi = 0;
        #pragma unroll
        for (int m = 1; m < 8; m++)
            if (magB[m] > bm) { bm = magB[m]; bmi = m; }
        bk = bmi * 256 + tl;
        #pragma unroll
        for (int o = 16; o > 0; o >>= 1) {
            float om = __shfl_down_sync(0xFFFFFFFFu, bm, o);
            int   ok = __shfl_down_sync(0xFFFFFFFFu, bk, o);
            if (om > bm) { bm = om; bk = ok; }
        }
        bm = __shfl_sync(0xFFFFFFFFu, bm, 0);
        bk = __shfl_sync(0xFFFFFFFFu, bk, 0);
        if ((bk & 255) == tl) magB[bk >> 8] = -1.0f;
        if (lane == r7) cand[56 + wrp * TOPK + r7] = make_float2(bm, __int_as_float(bk));
    }
    __syncthreads();

    // ---------------- phase 2: merge 56 candidates per channel -------------
    if (wrp < 2) {                           // warp 0 -> channel A, warp 1 -> B
        const float2* cs = cand + wrp * 56;
        float m0 = -3.0f, m1 = -3.0f; int k0 = 1, k1 = 1;
        if (lane < 28) {
            float2 e0 = cs[lane];      m0 = e0.x; k0 = __float_as_int(e0.y);
            float2 e1 = cs[lane + 28]; m1 = e1.x; k1 = __float_as_int(e1.y);
        }
        int savedK = 1;
        #pragma unroll
        for (int r7 = 0; r7 < TOPK; r7++) {
            float bm = m0; int bk = k0;
            if (m1 > bm) { bm = m1; bk = k1; }
            #pragma unroll
            for (int o = 16; o > 0; o >>= 1) {
                float om = __shfl_down_sync(0xFFFFFFFFu, bm, o);
                int   ok = __shfl_down_sync(0xFFFFFFFFu, bk, o);
                if (om > bm) { bm = om; bk = ok; }
            }
            bk = __shfl_sync(0xFFFFFFFFu, bk, 0);
            if (k0 == bk) m0 = -3.0f;
            if (k1 == bk) m1 = -3.0f;
            if (lane == r7) savedK = bk;
        }
        // extraction: lanes 0..6 each handle one winner
        if (lane < TOPK) {
            int k = savedK;
            float2 Zk = Z[SPAD(k)];
            float2 Zn = Z[SPAD(4096 - k)];
            float re, im;
            if (wrp == 0) { re = 0.5f * (Zk.x + Zn.x); im = 0.5f * (Zk.y - Zn.y); }
            else          { re = 0.5f * (Zk.y + Zn.y); im = 0.5f * (Zn.x - Zk.x); }
            float twoC = 2.0f * cospif((float)k * (1.0f / 2048.0f));
            g_params[(size_t)(b * D + d0 + wrp) * TOPK + lane] =
                make_float4(__int_as_float(k), re * (1.0f / 1024.0f),
                            im * (1.0f / 1024.0f), twoC);
        }
    }
}

// ---------------------------------------------------------------------------
// Kernel 2: Chebyshev reconstruction, 128-sample chunks, table seeds.
// sin(pi*m/2048) = g_costab[(m-1024)&4095].
// ---------------------------------------------------------------------------
__global__ __launch_bounds__(256)
void reconstruct_kernel(float* __restrict__ out) {
    const int d  = threadIdx.x;
    const int b  = blockIdx.y;
    const int t0 = blockIdx.x * 128;
    const size_t series = (size_t)b * D + d;

    float twoC[TOPK], g[TOPK], gp[TOPK];
    #pragma unroll
    for (int j = 0; j < TOPK; j++) {
        float4 p = g_params[series * TOPK + j];
        int k = __float_as_int(p.x);
        float C = p.y, S = p.z;
        twoC[j] = p.w;
        int m1 = (k * t0) & (T - 1);
        int m0 = (k * (t0 - 1)) & (T - 1);
        gp[j] = C * g_costab[m0] - S * g_costab[(m0 - 1024) & (T - 1)];
        g[j]  = C * g_costab[m1] - S * g_costab[(m1 - 1024) & (T - 1)];
    }

    float* orow = out + ((size_t)(b * T + t0)) * D + d;
    for (int tt = 0; tt < 128; tt += 2) {
        float a0 = 0.0f;
        #pragma unroll
        for (int j = 0; j < TOPK; j++) a0 += g[j];
        orow[(size_t)tt * D] = a0;
        #pragma unroll
        for (int j = 0; j < TOPK; j++)
            gp[j] = fmaf(twoC[j], g[j], -gp[j]);
        float a1 = 0.0f;
        #pragma unroll
        for (int j = 0; j < TOPK; j++) a1 += gp[j];
        orow[(size_t)(tt + 1) * D] = a1;
        #pragma unroll
        for (int j = 0; j < TOPK; j++)
            g[j] = fmaf(twoC[j], gp[j], -g[j]);
    }
}

// ---------------------------------------------------------------------------
extern "C" void kernel_launch(void* const* d_in, const int* in_sizes, int n_in,
                              void* d_out, int out_size) {
    const float* x = (const float*)d_in[0];
    float* out = (float*)d_out;

    const size_t smem_bytes = (SER_PAD + 112) * sizeof(float2);
    cudaFuncSetAttribute(fft_topk_kernel,
                         cudaFuncAttributeMaxDynamicSharedMemorySize,
                         (int)smem_bytes);

    fft_topk_kernel<<<NBLK, 256, smem_bytes>>>(x);
    reconstruct_kernel<<<dim3(T / 128, B), 256>>>(out);
}